// round 9
// baseline (speedup 1.0000x reference)
#include <cuda_runtime.h>
#include <cuda_bf16.h>
#include <cstdint>

// Problem constants
#define Bsz   256
#define Tsz   250
#define DIN   700
#define Hd    128
#define DOUT  20
#define KT    64            // k-tile
#define NKT   11            // 704 / 64

// Scratch
__device__ float g_h1[Tsz * Bsz * Hd];                 // h1_all[t][b][h]
__device__ __nv_bfloat16 g_Bh[NKT * 128 * KT];          // W1^T splits [kt][n][kk]
__device__ __nv_bfloat16 g_Bm[NKT * 128 * KT];
__device__ __nv_bfloat16 g_Bl[NKT * 128 * KT];

// ---- exact truncation split: a = h + m + l, each bf16-exact ---------------
__device__ __forceinline__ void bsplit(float a, float& h, float& m, float& l) {
    h = __uint_as_float(__float_as_uint(a) & 0xFFFF0000u);
    float r = a - h;                                    // exact
    m = __uint_as_float(__float_as_uint(r) & 0xFFFF0000u);
    l = r - m;                                          // exact, <=8 bits
}
__device__ __forceinline__ uint32_t hpack(float a, float b) {
    return __byte_perm(__float_as_uint(a), __float_as_uint(b), 0x7632);
}

// ---------------------------------------------------------------------------
// Prep: split W1 -> g_B{h,m,l}[kt][n][kk], zero pad k>=700
// ---------------------------------------------------------------------------
__global__ void prep_kernel(const float* __restrict__ W1)
{
    int idx = blockIdx.x * blockDim.x + threadIdx.x;
    if (idx >= NKT * 128 * KT) return;
    int kt = idx / (128 * KT);
    int r  = idx - kt * (128 * KT);
    int n  = r >> 6;
    int kk = r & 63;
    int k  = kt * KT + kk;
    float w = (k < DIN) ? W1[k * Hd + n] : 0.f;
    float h, m, l;
    bsplit(w, h, m, l);
    g_Bh[idx] = __float2bfloat16(h);
    g_Bm[idx] = __float2bfloat16(m);
    g_Bl[idx] = __float2bfloat16(l);
}

// ---------------------------------------------------------------------------
// mma.sync helpers (base sm_103 ISA)
// ---------------------------------------------------------------------------
__device__ __forceinline__ void mma_bf16(float* d, const uint32_t* a,
                                         const uint32_t* b) {
    asm volatile(
        "mma.sync.aligned.m16n8k16.row.col.f32.bf16.bf16.f32 "
        "{%0,%1,%2,%3}, {%4,%5,%6,%7}, {%8,%9}, {%0,%1,%2,%3};"
        : "+f"(d[0]), "+f"(d[1]), "+f"(d[2]), "+f"(d[3])
        : "r"(a[0]), "r"(a[1]), "r"(a[2]), "r"(a[3]), "r"(b[0]), "r"(b[1]));
}
__device__ __forceinline__ void ldsm4(uint32_t* r, uint32_t addr) {
    asm volatile("ldmatrix.sync.aligned.m8n8.x4.shared.b16 {%0,%1,%2,%3}, [%4];"
                 : "=r"(r[0]), "=r"(r[1]), "=r"(r[2]), "=r"(r[3]) : "r"(addr));
}
__device__ __forceinline__ uint32_t smem_u32(const void* p) {
    uint32_t a;
    asm("{ .reg .u64 t; cvta.to.shared.u64 t, %1; cvt.u32.u64 %0, t; }"
        : "=r"(a) : "l"(p));
    return a;
}
__device__ __forceinline__ void cp16(uint32_t dst, const void* src) {
    asm volatile("cp.async.cg.shared.global [%0], [%1], 16;"
                 :: "r"(dst), "l"(src));
}

// smem byte offsets: two full tile buffers (rows 64 bf16 = 128B, XOR-16 swz)
#define TB_AH   0
#define TB_AM   16384
#define TB_AL   32768
#define TB_BH   49152
#define TB_BM   65536
#define TB_BL   81920
#define TB_SIZE 98304
#define GS_BIAS (2 * TB_SIZE)
#define GS_BYTES (GS_BIAS + 512)          // 197,120 B (1 CTA/SM)

// ---------------------------------------------------------------------------
// Kernel 1: h1_all = x @ W1 + b1 via bf16x3 (6-product, fp32-accurate) HMMA.
// Double-buffered k-tiles. Per-ks: ALL 18 ldsm4 issue up front into
// dedicated registers (no WAR reloads), then 96 MMAs back-to-back in the
// SAME accumulation order as before (bit-identical h1).
// ---------------------------------------------------------------------------
__global__ void __launch_bounds__(256, 1) gemm1_kernel(
    const float* __restrict__ x,
    const float* __restrict__ b1)
{
    extern __shared__ char smg[];
    const uint32_t sbase = smem_u32(smg);
    const int tid  = threadIdx.x;
    const int wid  = tid >> 5;
    const int lane = tid & 31;
    const int mw   = wid & 1;
    const int nw   = wid >> 1;
    const int m0   = blockIdx.x * 128;

    if (tid < 128) ((float*)(smg + GS_BIAS))[tid] = b1[tid];

    float acc[4][4][4];
    #pragma unroll
    for (int i = 0; i < 4; i++)
        #pragma unroll
        for (int j = 0; j < 4; j++)
            #pragma unroll
            for (int c = 0; c < 4; c++) acc[i][j][c] = 0.f;

    const int arow = tid >> 1;
    const int akh  = tid & 1;
    const float* xrow = x + (size_t)(m0 + arow) * DIN;
    const uint32_t aswz = (uint32_t)((arow & 7) << 4);
    const uint32_t abase = (uint32_t)(arow * 128);

    const int ra = (lane & 7) + ((lane >> 3) & 1) * 8;
    const int ka = (lane >> 4) * 8;
    const int rb = (lane & 7) + (lane >> 4) * 8;
    const int kbl = ((lane >> 3) & 1) * 8;
    const uint32_t lswz = (uint32_t)((lane & 7) << 4);

    int bn[4], bkc[4];
    uint32_t bdst[4];
    #pragma unroll
    for (int u = 0; u < 4; u++) {
        int c = tid + u * 256;
        bn[u]  = c >> 3;
        bkc[u] = c & 7;
        bdst[u] = (uint32_t)(bn[u] * 128)
                + (((uint32_t)(bkc[u] * 16)) ^ ((uint32_t)((bn[u] & 7) << 4)));
    }

    float4 va[8];

    auto ldA = [&](int kt) {
        #pragma unroll
        for (int i = 0; i < 4; i++) {
            int kl = akh * 32 + i * 8;
            int gk = kt * KT + kl;
            va[i*2+0] = (gk <= DIN - 4) ? *(const float4*)(xrow + gk)
                                        : make_float4(0.f, 0.f, 0.f, 0.f);
            va[i*2+1] = (gk + 4 <= DIN - 4) ? *(const float4*)(xrow + gk + 4)
                                            : make_float4(0.f, 0.f, 0.f, 0.f);
        }
    };
    auto cpB = [&](int kt, uint32_t buf) {
        #pragma unroll
        for (int u = 0; u < 4; u++) {
            int src = kt * (128 * KT) + bn[u] * KT + bkc[u] * 8;
            cp16(buf + TB_BH + bdst[u], g_Bh + src);
            cp16(buf + TB_BM + bdst[u], g_Bm + src);
            cp16(buf + TB_BL + bdst[u], g_Bl + src);
        }
        asm volatile("cp.async.commit_group;" ::: "memory");
    };
    auto stsA = [&](char* bufp) {
        #pragma unroll
        for (int i = 0; i < 4; i++) {
            int kl = akh * 32 + i * 8;
            float4 v0 = va[i*2+0], v1 = va[i*2+1];
            float h[8], m[8], l[8];
            bsplit(v0.x, h[0], m[0], l[0]); bsplit(v0.y, h[1], m[1], l[1]);
            bsplit(v0.z, h[2], m[2], l[2]); bsplit(v0.w, h[3], m[3], l[3]);
            bsplit(v1.x, h[4], m[4], l[4]); bsplit(v1.y, h[5], m[5], l[5]);
            bsplit(v1.z, h[6], m[6], l[6]); bsplit(v1.w, h[7], m[7], l[7]);
            uint32_t soff = abase + (((uint32_t)(kl * 2)) ^ aswz);
            *(uint4*)(bufp + TB_AH + soff) =
                make_uint4(hpack(h[0],h[1]), hpack(h[2],h[3]),
                           hpack(h[4],h[5]), hpack(h[6],h[7]));
            *(uint4*)(bufp + TB_AM + soff) =
                make_uint4(hpack(m[0],m[1]), hpack(m[2],m[3]),
                           hpack(m[4],m[5]), hpack(m[6],m[7]));
            *(uint4*)(bufp + TB_AL + soff) =
                make_uint4(hpack(l[0],l[1]), hpack(l[2],l[3]),
                           hpack(l[4],l[5]), hpack(l[6],l[7]));
        }
    };

    ldA(0);
    cpB(0, sbase);
    stsA(smg);
    asm volatile("cp.async.wait_group 0;" ::: "memory");
    __syncthreads();

    for (int kt = 0; kt < NKT; kt++) {
        const uint32_t cbuf = (uint32_t)(kt & 1) * TB_SIZE;
        const uint32_t nbuf = (uint32_t)((kt + 1) & 1) * TB_SIZE;

        if (kt + 1 < NKT) {
            ldA(kt + 1);
            cpB(kt + 1, sbase + nbuf);
        }

        #pragma unroll
        for (int ks = 0; ks < 4; ks++) {
            const int kb = ks * 16;
            uint32_t ah[4][4], am[4][4], al[4][4];
            uint32_t bh[4][2], bm[4][2], bl[4][2];

            // ---- ALL fragment loads up front (dedicated registers) ----
            #pragma unroll
            for (int mt = 0; mt < 4; mt++) {
                uint32_t row = (uint32_t)(mw * 64 + mt * 16 + ra);
                uint32_t off = row * 128 + (((uint32_t)((kb + ka) * 2)) ^ lswz);
                ldsm4(ah[mt], sbase + cbuf + TB_AH + off);
                ldsm4(am[mt], sbase + cbuf + TB_AM + off);
                ldsm4(al[mt], sbase + cbuf + TB_AL + off);
            }
            #pragma unroll
            for (int g = 0; g < 2; g++) {
                uint32_t row = (uint32_t)(nw * 32 + g * 16 + rb);
                uint32_t off = row * 128 + (((uint32_t)((kb + kbl) * 2)) ^ lswz);
                uint32_t r4[4];
                ldsm4(r4, sbase + cbuf + TB_BH + off);
                bh[g*2][0] = r4[0]; bh[g*2][1] = r4[1];
                bh[g*2+1][0] = r4[2]; bh[g*2+1][1] = r4[3];
                ldsm4(r4, sbase + cbuf + TB_BM + off);
                bm[g*2][0] = r4[0]; bm[g*2][1] = r4[1];
                bm[g*2+1][0] = r4[2]; bm[g*2+1][1] = r4[3];
                ldsm4(r4, sbase + cbuf + TB_BL + off);
                bl[g*2][0] = r4[0]; bl[g*2][1] = r4[1];
                bl[g*2+1][0] = r4[2]; bl[g*2+1][1] = r4[3];
            }

            // ---- 96 MMAs, same accumulation order as before ----
            #pragma unroll
            for (int mt = 0; mt < 4; mt++)
                #pragma unroll
                for (int nt = 0; nt < 4; nt++) {
                    mma_bf16(acc[mt][nt], am[mt], bm[nt]);   // mm
                    mma_bf16(acc[mt][nt], ah[mt], bm[nt]);   // hm
                }
            #pragma unroll
            for (int mt = 0; mt < 4; mt++)
                #pragma unroll
                for (int nt = 0; nt < 4; nt++)
                    mma_bf16(acc[mt][nt], am[mt], bh[nt]);   // mh
            #pragma unroll
            for (int mt = 0; mt < 4; mt++)
                #pragma unroll
                for (int nt = 0; nt < 4; nt++) {
                    mma_bf16(acc[mt][nt], ah[mt], bl[nt]);   // hl
                    mma_bf16(acc[mt][nt], al[mt], bh[nt]);   // lh
                    mma_bf16(acc[mt][nt], ah[mt], bh[nt]);   // hh
                }
        }

        if (kt + 1 < NKT) {
            stsA(smg + nbuf);
            asm volatile("cp.async.wait_group 0;" ::: "memory");
            __syncthreads();
        }
    }

    const float* sb1 = (const float*)(smg + GS_BIAS);
    const int r_lo = lane >> 2;
    const int c_lo = (lane & 3) * 2;
    #pragma unroll
    for (int mt = 0; mt < 4; mt++) {
        #pragma unroll
        for (int half = 0; half < 2; half++) {
            int mrow = m0 + mw * 64 + mt * 16 + r_lo + half * 8;
            int b = mrow / Tsz;
            int t = mrow - b * Tsz;
            float* orow = g_h1 + (size_t)t * (Bsz * Hd) + b * Hd;
            #pragma unroll
            for (int nt = 0; nt < 4; nt++) {
                int c = nw * 32 + nt * 8 + c_lo;
                float2 v;
                v.x = acc[mt][nt][half * 2 + 0] + sb1[c];
                v.y = acc[mt][nt][half * 2 + 1] + sb1[c + 1];
                *(float2*)(orow + c) = v;
            }
        }
    }
}

// ---------------------------------------------------------------------------
// Kernel 2: recurrent LIF — one warp/sample, 4 neurons/thread (R7 verbatim,
// best known: ~134us). Ballot masks, zero barriers in the loop.
// ---------------------------------------------------------------------------
#define SM_W0   0
#define SM_W1   16384
#define SM_W2   32768
#define SM_W3   49152
#define SM_RCB1 51712
#define SM_B2C  51840
#define SM_FLOATS 51968
#define SM_BYTES  (SM_FLOATS * 4)

__global__ void __launch_bounds__(256, 1) rec_kernel(
    const float* __restrict__ rcW1, const float* __restrict__ rcb1,
    const float* __restrict__ W2,   const float* __restrict__ b2,
    const float* __restrict__ rcW2, const float* __restrict__ rcb2,
    const float* __restrict__ W3,   const float* __restrict__ b3,
    float* __restrict__ out)
{
    extern __shared__ float sm[];
    float* sW0   = sm + SM_W0;
    float* sW1   = sm + SM_W1;
    float* sW2   = sm + SM_W2;
    float* sW3   = sm + SM_W3;
    float* srcb1 = sm + SM_RCB1;
    float* sb2c  = sm + SM_B2C;

    const int tid = threadIdx.x;

    {
        const float4* a = (const float4*)rcW1;
        const float4* c = (const float4*)W2;
        const float4* d = (const float4*)rcW2;
        float4* o0 = (float4*)sW0; float4* o1 = (float4*)sW1; float4* o2 = (float4*)sW2;
        for (int i = tid; i < (Hd * Hd) / 4; i += 256) {
            o0[i] = a[i]; o1[i] = c[i]; o2[i] = d[i];
        }
    }
    for (int i = tid; i < Hd * DOUT; i += 256) sW3[i] = W3[i];
    if (tid < Hd) {
        srcb1[tid] = rcb1[tid];
        sb2c[tid]  = b2[tid] + rcb2[tid];
    }
    __syncthreads();

    const int wid  = tid >> 5;
    if (wid >= 2) return;

    const int lane = tid & 31;
    const int b    = blockIdx.x * 2 + wid;
    const int j0   = lane * 4;

    const float4 rcb1_r = *(const float4*)(srcb1 + j0);
    const float4 b2c_r  = *(const float4*)(sb2c + j0);

    float4 v1 = make_float4(0.f, 0.f, 0.f, 0.f);
    float4 v2 = make_float4(0.f, 0.f, 0.f, 0.f);
    float  acc = 0.f;
    unsigned m1[4] = {0u,0u,0u,0u};
    unsigned m2[4] = {0u,0u,0u,0u};

    const float* h1p = g_h1 + b * Hd + j0;
    float4 h1v = *(const float4*)h1p;

    const float* sW0j = sW0 + j0;
    const float* sW1j = sW1 + j0;
    const float* sW2j = sW2 + j0;

    for (int t = 0; t < Tsz; t++) {
        float4 h1n = (t + 1 < Tsz)
            ? *(const float4*)(h1p + (size_t)(t + 1) * (Bsz * Hd))
            : make_float4(0.f, 0.f, 0.f, 0.f);

        float4 u;
        u.x = h1v.x + rcb1_r.x; u.y = h1v.y + rcb1_r.y;
        u.z = h1v.z + rcb1_r.z; u.w = h1v.w + rcb1_r.w;
        #pragma unroll
        for (int c = 0; c < 4; c++) {
            unsigned mm = m1[c];
            while (mm) {
                int bit = __ffs(mm) - 1; mm &= mm - 1u;
                float4 w = *(const float4*)(sW0j + ((bit << 2) | c) * Hd);
                u.x += w.x; u.y += w.y; u.z += w.z; u.w += w.w;
            }
        }
        v1.x += (u.x - v1.x) * 0.5f;  v1.y += (u.y - v1.y) * 0.5f;
        v1.z += (u.z - v1.z) * 0.5f;  v1.w += (u.w - v1.w) * 0.5f;
        bool s0 = v1.x >= 1.f, s1b = v1.y >= 1.f, s2b = v1.z >= 1.f, s3 = v1.w >= 1.f;
        if (s0) v1.x = 0.f;  if (s1b) v1.y = 0.f;
        if (s2b) v1.z = 0.f; if (s3) v1.w = 0.f;
        m1[0] = __ballot_sync(0xffffffffu, s0);
        m1[1] = __ballot_sync(0xffffffffu, s1b);
        m1[2] = __ballot_sync(0xffffffffu, s2b);
        m1[3] = __ballot_sync(0xffffffffu, s3);

        float4 u2 = make_float4(b2c_r.x, b2c_r.y, b2c_r.z, b2c_r.w);
        #pragma unroll
        for (int c = 0; c < 4; c++) {
            unsigned mm = m1[c];
            while (mm) {
                int bit = __ffs(mm) - 1; mm &= mm - 1u;
                float4 w = *(const float4*)(sW1j + ((bit << 2) | c) * Hd);
                u2.x += w.x; u2.y += w.y; u2.z += w.z; u2.w += w.w;
            }
        }
        #pragma unroll
        for (int c = 0; c < 4; c++) {
            unsigned mm = m2[c];
            while (mm) {
                int bit = __ffs(mm) - 1; mm &= mm - 1u;
                float4 w = *(const float4*)(sW2j + ((bit << 2) | c) * Hd);
                u2.x += w.x; u2.y += w.y; u2.z += w.z; u2.w += w.w;
            }
        }
        v2.x += (u2.x - v2.x) * 0.5f;  v2.y += (u2.y - v2.y) * 0.5f;
        v2.z += (u2.z - v2.z) * 0.5f;  v2.w += (u2.w - v2.w) * 0.5f;
        s0 = v2.x >= 1.f; s1b = v2.y >= 1.f; s2b = v2.z >= 1.f; s3 = v2.w >= 1.f;
        if (s0) v2.x = 0.f;  if (s1b) v2.y = 0.f;
        if (s2b) v2.z = 0.f; if (s3) v2.w = 0.f;
        m2[0] = __ballot_sync(0xffffffffu, s0);
        m2[1] = __ballot_sync(0xffffffffu, s1b);
        m2[2] = __ballot_sync(0xffffffffu, s2b);
        m2[3] = __ballot_sync(0xffffffffu, s3);

        if (lane < DOUT) {
            float a = 0.f;
            #pragma unroll
            for (int c = 0; c < 4; c++) {
                unsigned mm = m2[c];
                while (mm) {
                    int bit = __ffs(mm) - 1; mm &= mm - 1u;
                    a += sW3[((bit << 2) | c) * DOUT + lane];
                }
            }
            acc += a;
        }
        h1v = h1n;
    }

    if (lane < DOUT)
        out[b * DOUT + lane] = acc + (float)Tsz * b3[lane];
}

// ---------------------------------------------------------------------------
// Launch
// ---------------------------------------------------------------------------
extern "C" void kernel_launch(void* const* d_in, const int* in_sizes, int n_in,
                              void* d_out, int out_size)
{
    const float* x    = (const float*)d_in[0];
    const float* W1   = (const float*)d_in[1];
    const float* b1   = (const float*)d_in[2];
    const float* rcW1 = (const float*)d_in[3];
    const float* rcb1 = (const float*)d_in[4];
    const float* W2   = (const float*)d_in[5];
    const float* b2   = (const float*)d_in[6];
    const float* rcW2 = (const float*)d_in[7];
    const float* rcb2 = (const float*)d_in[8];
    const float* W3   = (const float*)d_in[9];
    const float* b3   = (const float*)d_in[10];
    float* out = (float*)d_out;

    cudaFuncSetAttribute(gemm1_kernel,
                         cudaFuncAttributeMaxDynamicSharedMemorySize, GS_BYTES);
    cudaFuncSetAttribute(rec_kernel,
                         cudaFuncAttributeMaxDynamicSharedMemorySize, SM_BYTES);

    // 0) split W1 into bf16 h/m/l tiles
    prep_kernel<<<(NKT * 128 * KT + 255) / 256, 256>>>(W1);

    // 1) h1_all = x @ W1 + b1 (bf16x3 HMMA, all-fragments-up-front schedule)
    gemm1_kernel<<<(Bsz * Tsz) / 128, 256, GS_BYTES>>>(x, b1);

    // 2) recurrent LIF loop (R7 verbatim)
    rec_kernel<<<Bsz / 2, 256, SM_BYTES>>>(rcW1, rcb1, W2, b2,
                                           rcW2, rcb2, W3, b3, out);
}

// round 10
// speedup vs baseline: 1.2988x; 1.2988x over previous
#include <cuda_runtime.h>
#include <cuda_bf16.h>
#include <cuda_fp16.h>
#include <cstdint>

// Problem constants
#define Bsz   256
#define Tsz   250
#define DIN   700
#define Hd    128
#define DOUT  20
#define KT    64            // k-tile
#define NKT   11            // 704 / 64

// Scratch
__device__ float g_h1[Tsz * Bsz * Hd];                 // h1_all[t][b][h]
__device__ __half g_Bh[NKT * 128 * KT];                 // W1^T fp16 splits [kt][n][kk]
__device__ __half g_Bm[NKT * 128 * KT];

// ---------------------------------------------------------------------------
// Prep: fp16 two-term split of W1 -> g_B{h,m}[kt][n][kk], zero pad k>=700
// ---------------------------------------------------------------------------
__global__ void prep_kernel(const float* __restrict__ W1)
{
    int idx = blockIdx.x * blockDim.x + threadIdx.x;
    if (idx >= NKT * 128 * KT) return;
    int kt = idx / (128 * KT);
    int r  = idx - kt * (128 * KT);
    int n  = r >> 6;
    int kk = r & 63;
    int k  = kt * KT + kk;
    float w = (k < DIN) ? W1[k * Hd + n] : 0.f;
    __half h = __float2half_rn(w);
    float  rm = w - __half2float(h);
    __half m = __float2half_rn(rm);
    g_Bh[idx] = h;
    g_Bm[idx] = m;
}

// ---------------------------------------------------------------------------
// mma.sync helpers (base sm_103 ISA)
// ---------------------------------------------------------------------------
__device__ __forceinline__ void mma_f16(float* d, const uint32_t* a,
                                        const uint32_t* b) {
    asm volatile(
        "mma.sync.aligned.m16n8k16.row.col.f32.f16.f16.f32 "
        "{%0,%1,%2,%3}, {%4,%5,%6,%7}, {%8,%9}, {%0,%1,%2,%3};"
        : "+f"(d[0]), "+f"(d[1]), "+f"(d[2]), "+f"(d[3])
        : "r"(a[0]), "r"(a[1]), "r"(a[2]), "r"(a[3]), "r"(b[0]), "r"(b[1]));
}
__device__ __forceinline__ void ldsm4(uint32_t* r, uint32_t addr) {
    asm volatile("ldmatrix.sync.aligned.m8n8.x4.shared.b16 {%0,%1,%2,%3}, [%4];"
                 : "=r"(r[0]), "=r"(r[1]), "=r"(r[2]), "=r"(r[3]) : "r"(addr));
}
__device__ __forceinline__ uint32_t smem_u32(const void* p) {
    uint32_t a;
    asm("{ .reg .u64 t; cvta.to.shared.u64 t, %1; cvt.u32.u64 %0, t; }"
        : "=r"(a) : "l"(p));
    return a;
}
__device__ __forceinline__ void cp16(uint32_t dst, const void* src) {
    asm volatile("cp.async.cg.shared.global [%0], [%1], 16;"
                 :: "r"(dst), "l"(src));
}

// smem: two tile buffers (rows 64 fp16 = 128B, XOR-16 swizzle on row&7)
#define TB_AH   0
#define TB_AM   16384
#define TB_BH   32768
#define TB_BM   49152
#define TB_SIZE 65536
#define GS_BIAS (2 * TB_SIZE)
#define GS_BYTES (GS_BIAS + 512)          // 131,584 B (1 CTA/SM)

// ---------------------------------------------------------------------------
// Kernel 1: h1_all = x @ W1 + b1 via fp16x2 (3-product) HMMA.
// a = h + m exactly captures 22 mantissa bits; D = mh + hm + hh in fp32 acc.
// Double-buffered k-tiles, cp.async for B, A staged in regs.
// ---------------------------------------------------------------------------
__global__ void __launch_bounds__(256, 1) gemm1_kernel(
    const float* __restrict__ x,
    const float* __restrict__ b1)
{
    extern __shared__ char smg[];
    const uint32_t sbase = smem_u32(smg);
    const int tid  = threadIdx.x;
    const int wid  = tid >> 5;
    const int lane = tid & 31;
    const int mw   = wid & 1;
    const int nw   = wid >> 1;
    const int m0   = blockIdx.x * 128;

    if (tid < 128) ((float*)(smg + GS_BIAS))[tid] = b1[tid];

    float acc[4][4][4];
    #pragma unroll
    for (int i = 0; i < 4; i++)
        #pragma unroll
        for (int j = 0; j < 4; j++)
            #pragma unroll
            for (int c = 0; c < 4; c++) acc[i][j][c] = 0.f;

    const int arow = tid >> 1;
    const int akh  = tid & 1;
    const float* xrow = x + (size_t)(m0 + arow) * DIN;
    const uint32_t aswz = (uint32_t)((arow & 7) << 4);
    const uint32_t abase = (uint32_t)(arow * 128);

    const int ra = (lane & 7) + ((lane >> 3) & 1) * 8;
    const int ka = (lane >> 4) * 8;
    const int rb = (lane & 7) + (lane >> 4) * 8;
    const int kbl = ((lane >> 3) & 1) * 8;
    const uint32_t lswz = (uint32_t)((lane & 7) << 4);

    int bn[4], bkc[4];
    uint32_t bdst[4];
    #pragma unroll
    for (int u = 0; u < 4; u++) {
        int c = tid + u * 256;
        bn[u]  = c >> 3;
        bkc[u] = c & 7;
        bdst[u] = (uint32_t)(bn[u] * 128)
                + (((uint32_t)(bkc[u] * 16)) ^ ((uint32_t)((bn[u] & 7) << 4)));
    }

    float4 va[8];

    auto ldA = [&](int kt) {
        #pragma unroll
        for (int i = 0; i < 4; i++) {
            int kl = akh * 32 + i * 8;
            int gk = kt * KT + kl;
            va[i*2+0] = (gk <= DIN - 4) ? *(const float4*)(xrow + gk)
                                        : make_float4(0.f, 0.f, 0.f, 0.f);
            va[i*2+1] = (gk + 4 <= DIN - 4) ? *(const float4*)(xrow + gk + 4)
                                            : make_float4(0.f, 0.f, 0.f, 0.f);
        }
    };
    auto cpB = [&](int kt, uint32_t buf) {
        #pragma unroll
        for (int u = 0; u < 4; u++) {
            int src = kt * (128 * KT) + bn[u] * KT + bkc[u] * 8;
            cp16(buf + TB_BH + bdst[u], g_Bh + src);
            cp16(buf + TB_BM + bdst[u], g_Bm + src);
        }
        asm volatile("cp.async.commit_group;" ::: "memory");
    };
    auto stsA = [&](char* bufp) {
        #pragma unroll
        for (int i = 0; i < 4; i++) {
            int kl = akh * 32 + i * 8;
            float a[8];
            a[0]=va[i*2].x; a[1]=va[i*2].y; a[2]=va[i*2].z; a[3]=va[i*2].w;
            a[4]=va[i*2+1].x; a[5]=va[i*2+1].y; a[6]=va[i*2+1].z; a[7]=va[i*2+1].w;
            uint32_t hw[4], mw4[4];
            #pragma unroll
            for (int p = 0; p < 4; p++) {
                __half2 h2 = __float22half2_rn(make_float2(a[2*p], a[2*p+1]));
                float2 hf = __half22float2(h2);
                __half2 m2 = __float22half2_rn(
                    make_float2(a[2*p] - hf.x, a[2*p+1] - hf.y));
                hw[p]  = *reinterpret_cast<uint32_t*>(&h2);
                mw4[p] = *reinterpret_cast<uint32_t*>(&m2);
            }
            uint32_t soff = abase + (((uint32_t)(kl * 2)) ^ aswz);
            *(uint4*)(bufp + TB_AH + soff) = make_uint4(hw[0],hw[1],hw[2],hw[3]);
            *(uint4*)(bufp + TB_AM + soff) = make_uint4(mw4[0],mw4[1],mw4[2],mw4[3]);
        }
    };

    ldA(0);
    cpB(0, sbase);
    stsA(smg);
    asm volatile("cp.async.wait_group 0;" ::: "memory");
    __syncthreads();

    for (int kt = 0; kt < NKT; kt++) {
        const uint32_t cbuf = (uint32_t)(kt & 1) * TB_SIZE;
        const uint32_t nbuf = (uint32_t)((kt + 1) & 1) * TB_SIZE;

        if (kt + 1 < NKT) {
            ldA(kt + 1);
            cpB(kt + 1, sbase + nbuf);
        }

        #pragma unroll
        for (int ks = 0; ks < 4; ks++) {
            const int kb = ks * 16;
            uint32_t ah[4][4], am[4][4], bh[4][2], bm[4][2];

            #pragma unroll
            for (int mt = 0; mt < 4; mt++) {
                uint32_t row = (uint32_t)(mw * 64 + mt * 16 + ra);
                uint32_t off = row * 128 + (((uint32_t)((kb + ka) * 2)) ^ lswz);
                ldsm4(ah[mt], sbase + cbuf + TB_AH + off);
                ldsm4(am[mt], sbase + cbuf + TB_AM + off);
            }
            #pragma unroll
            for (int g = 0; g < 2; g++) {
                uint32_t row = (uint32_t)(nw * 32 + g * 16 + rb);
                uint32_t off = row * 128 + (((uint32_t)((kb + kbl) * 2)) ^ lswz);
                uint32_t r4[4];
                ldsm4(r4, sbase + cbuf + TB_BH + off);
                bh[g*2][0] = r4[0]; bh[g*2][1] = r4[1];
                bh[g*2+1][0] = r4[2]; bh[g*2+1][1] = r4[3];
                ldsm4(r4, sbase + cbuf + TB_BM + off);
                bm[g*2][0] = r4[0]; bm[g*2][1] = r4[1];
                bm[g*2+1][0] = r4[2]; bm[g*2+1][1] = r4[3];
            }

            // 48 MMAs: small terms first (mh, hm), then hh
            #pragma unroll
            for (int mt = 0; mt < 4; mt++)
                #pragma unroll
                for (int nt = 0; nt < 4; nt++) {
                    mma_f16(acc[mt][nt], am[mt], bh[nt]);   // mh
                    mma_f16(acc[mt][nt], ah[mt], bm[nt]);   // hm
                }
            #pragma unroll
            for (int mt = 0; mt < 4; mt++)
                #pragma unroll
                for (int nt = 0; nt < 4; nt++)
                    mma_f16(acc[mt][nt], ah[mt], bh[nt]);   // hh
        }

        if (kt + 1 < NKT) {
            stsA(smg + nbuf);
            asm volatile("cp.async.wait_group 0;" ::: "memory");
            __syncthreads();
        }
    }

    const float* sb1 = (const float*)(smg + GS_BIAS);
    const int r_lo = lane >> 2;
    const int c_lo = (lane & 3) * 2;
    #pragma unroll
    for (int mt = 0; mt < 4; mt++) {
        #pragma unroll
        for (int half = 0; half < 2; half++) {
            int mrow = m0 + mw * 64 + mt * 16 + r_lo + half * 8;
            int b = mrow / Tsz;
            int t = mrow - b * Tsz;
            float* orow = g_h1 + (size_t)t * (Bsz * Hd) + b * Hd;
            #pragma unroll
            for (int nt = 0; nt < 4; nt++) {
                int c = nw * 32 + nt * 8 + c_lo;
                float2 v;
                v.x = acc[mt][nt][half * 2 + 0] + sb1[c];
                v.y = acc[mt][nt][half * 2 + 1] + sb1[c + 1];
                *(float2*)(orow + c) = v;
            }
        }
    }
}

// ---------------------------------------------------------------------------
// Kernel 2: recurrent LIF — one warp/sample, 4 neurons/thread (R7 verbatim,
// best known: ~134us). Ballot masks, zero barriers in the loop.
// ---------------------------------------------------------------------------
#define SM_W0   0
#define SM_W1   16384
#define SM_W2   32768
#define SM_W3   49152
#define SM_RCB1 51712
#define SM_B2C  51840
#define SM_FLOATS 51968
#define SM_BYTES  (SM_FLOATS * 4)

__global__ void __launch_bounds__(256, 1) rec_kernel(
    const float* __restrict__ rcW1, const float* __restrict__ rcb1,
    const float* __restrict__ W2,   const float* __restrict__ b2,
    const float* __restrict__ rcW2, const float* __restrict__ rcb2,
    const float* __restrict__ W3,   const float* __restrict__ b3,
    float* __restrict__ out)
{
    extern __shared__ float sm[];
    float* sW0   = sm + SM_W0;
    float* sW1   = sm + SM_W1;
    float* sW2   = sm + SM_W2;
    float* sW3   = sm + SM_W3;
    float* srcb1 = sm + SM_RCB1;
    float* sb2c  = sm + SM_B2C;

    const int tid = threadIdx.x;

    {
        const float4* a = (const float4*)rcW1;
        const float4* c = (const float4*)W2;
        const float4* d = (const float4*)rcW2;
        float4* o0 = (float4*)sW0; float4* o1 = (float4*)sW1; float4* o2 = (float4*)sW2;
        for (int i = tid; i < (Hd * Hd) / 4; i += 256) {
            o0[i] = a[i]; o1[i] = c[i]; o2[i] = d[i];
        }
    }
    for (int i = tid; i < Hd * DOUT; i += 256) sW3[i] = W3[i];
    if (tid < Hd) {
        srcb1[tid] = rcb1[tid];
        sb2c[tid]  = b2[tid] + rcb2[tid];
    }
    __syncthreads();

    const int wid  = tid >> 5;
    if (wid >= 2) return;

    const int lane = tid & 31;
    const int b    = blockIdx.x * 2 + wid;
    const int j0   = lane * 4;

    const float4 rcb1_r = *(const float4*)(srcb1 + j0);
    const float4 b2c_r  = *(const float4*)(sb2c + j0);

    float4 v1 = make_float4(0.f, 0.f, 0.f, 0.f);
    float4 v2 = make_float4(0.f, 0.f, 0.f, 0.f);
    float  acc = 0.f;
    unsigned m1[4] = {0u,0u,0u,0u};
    unsigned m2[4] = {0u,0u,0u,0u};

    const float* h1p = g_h1 + b * Hd + j0;
    float4 h1v = *(const float4*)h1p;

    const float* sW0j = sW0 + j0;
    const float* sW1j = sW1 + j0;
    const float* sW2j = sW2 + j0;

    for (int t = 0; t < Tsz; t++) {
        float4 h1n = (t + 1 < Tsz)
            ? *(const float4*)(h1p + (size_t)(t + 1) * (Bsz * Hd))
            : make_float4(0.f, 0.f, 0.f, 0.f);

        float4 u;
        u.x = h1v.x + rcb1_r.x; u.y = h1v.y + rcb1_r.y;
        u.z = h1v.z + rcb1_r.z; u.w = h1v.w + rcb1_r.w;
        #pragma unroll
        for (int c = 0; c < 4; c++) {
            unsigned mm = m1[c];
            while (mm) {
                int bit = __ffs(mm) - 1; mm &= mm - 1u;
                float4 w = *(const float4*)(sW0j + ((bit << 2) | c) * Hd);
                u.x += w.x; u.y += w.y; u.z += w.z; u.w += w.w;
            }
        }
        v1.x += (u.x - v1.x) * 0.5f;  v1.y += (u.y - v1.y) * 0.5f;
        v1.z += (u.z - v1.z) * 0.5f;  v1.w += (u.w - v1.w) * 0.5f;
        bool s0 = v1.x >= 1.f, s1b = v1.y >= 1.f, s2b = v1.z >= 1.f, s3 = v1.w >= 1.f;
        if (s0) v1.x = 0.f;  if (s1b) v1.y = 0.f;
        if (s2b) v1.z = 0.f; if (s3) v1.w = 0.f;
        m1[0] = __ballot_sync(0xffffffffu, s0);
        m1[1] = __ballot_sync(0xffffffffu, s1b);
        m1[2] = __ballot_sync(0xffffffffu, s2b);
        m1[3] = __ballot_sync(0xffffffffu, s3);

        float4 u2 = make_float4(b2c_r.x, b2c_r.y, b2c_r.z, b2c_r.w);
        #pragma unroll
        for (int c = 0; c < 4; c++) {
            unsigned mm = m1[c];
            while (mm) {
                int bit = __ffs(mm) - 1; mm &= mm - 1u;
                float4 w = *(const float4*)(sW1j + ((bit << 2) | c) * Hd);
                u2.x += w.x; u2.y += w.y; u2.z += w.z; u2.w += w.w;
            }
        }
        #pragma unroll
        for (int c = 0; c < 4; c++) {
            unsigned mm = m2[c];
            while (mm) {
                int bit = __ffs(mm) - 1; mm &= mm - 1u;
                float4 w = *(const float4*)(sW2j + ((bit << 2) | c) * Hd);
                u2.x += w.x; u2.y += w.y; u2.z += w.z; u2.w += w.w;
            }
        }
        v2.x += (u2.x - v2.x) * 0.5f;  v2.y += (u2.y - v2.y) * 0.5f;
        v2.z += (u2.z - v2.z) * 0.5f;  v2.w += (u2.w - v2.w) * 0.5f;
        s0 = v2.x >= 1.f; s1b = v2.y >= 1.f; s2b = v2.z >= 1.f; s3 = v2.w >= 1.f;
        if (s0) v2.x = 0.f;  if (s1b) v2.y = 0.f;
        if (s2b) v2.z = 0.f; if (s3) v2.w = 0.f;
        m2[0] = __ballot_sync(0xffffffffu, s0);
        m2[1] = __ballot_sync(0xffffffffu, s1b);
        m2[2] = __ballot_sync(0xffffffffu, s2b);
        m2[3] = __ballot_sync(0xffffffffu, s3);

        if (lane < DOUT) {
            float a = 0.f;
            #pragma unroll
            for (int c = 0; c < 4; c++) {
                unsigned mm = m2[c];
                while (mm) {
                    int bit = __ffs(mm) - 1; mm &= mm - 1u;
                    a += sW3[((bit << 2) | c) * DOUT + lane];
                }
            }
            acc += a;
        }
        h1v = h1n;
    }

    if (lane < DOUT)
        out[b * DOUT + lane] = acc + (float)Tsz * b3[lane];
}

// ---------------------------------------------------------------------------
// Launch
// ---------------------------------------------------------------------------
extern "C" void kernel_launch(void* const* d_in, const int* in_sizes, int n_in,
                              void* d_out, int out_size)
{
    const float* x    = (const float*)d_in[0];
    const float* W1   = (const float*)d_in[1];
    const float* b1   = (const float*)d_in[2];
    const float* rcW1 = (const float*)d_in[3];
    const float* rcb1 = (const float*)d_in[4];
    const float* W2   = (const float*)d_in[5];
    const float* b2   = (const float*)d_in[6];
    const float* rcW2 = (const float*)d_in[7];
    const float* rcb2 = (const float*)d_in[8];
    const float* W3   = (const float*)d_in[9];
    const float* b3   = (const float*)d_in[10];
    float* out = (float*)d_out;

    cudaFuncSetAttribute(gemm1_kernel,
                         cudaFuncAttributeMaxDynamicSharedMemorySize, GS_BYTES);
    cudaFuncSetAttribute(rec_kernel,
                         cudaFuncAttributeMaxDynamicSharedMemorySize, SM_BYTES);

    // 0) fp16 two-term split of W1
    prep_kernel<<<(NKT * 128 * KT + 255) / 256, 256>>>(W1);

    // 1) h1_all = x @ W1 + b1 (fp16x2 three-product HMMA)
    gemm1_kernel<<<(Bsz * Tsz) / 128, 256, GS_BYTES>>>(x, b1);

    // 2) recurrent LIF loop (R7 verbatim)
    rec_kernel<<<Bsz / 2, 256, SM_BYTES>>>(rcW1, rcb1, W2, b2,
                                           rcW2, rcb2, W3, b3, out);
}

// round 11
// speedup vs baseline: 1.4110x; 1.0864x over previous
#include <cuda_runtime.h>
#include <cuda_bf16.h>
#include <cuda_fp16.h>
#include <cstdint>

// Problem constants
#define Bsz   256
#define Tsz   250
#define DIN   700
#define Hd    128
#define DOUT  20
#define KT    64            // k-tile
#define NKT   11            // 704 / 64

#define REC_CTAS 32         // 8 samples per CTA
#define GEMM_TILES (Tsz * 2)

// Scratch
__device__ float g_h1[Tsz * Bsz * Hd];                 // h1_all[t][b][h]
__device__ __half g_Bh[NKT * 128 * KT];                 // W1^T fp16 splits [kt][n][kk]
__device__ __half g_Bm[NKT * 128 * KT];
__device__ int    g_flag[Tsz];                          // per-timestep arrivals (2 = ready)

// ---------------------------------------------------------------------------
// Prep: fp16 two-term split of W1 -> g_B{h,m}[kt][n][kk]; zero g_flag.
// ---------------------------------------------------------------------------
__global__ void prep_kernel(const float* __restrict__ W1)
{
    int idx = blockIdx.x * blockDim.x + threadIdx.x;
    if (idx < Tsz) g_flag[idx] = 0;
    if (idx >= NKT * 128 * KT) return;
    int kt = idx / (128 * KT);
    int r  = idx - kt * (128 * KT);
    int n  = r >> 6;
    int kk = r & 63;
    int k  = kt * KT + kk;
    float w = (k < DIN) ? W1[k * Hd + n] : 0.f;
    __half h = __float2half_rn(w);
    float  rm = w - __half2float(h);
    g_Bh[idx] = h;
    g_Bm[idx] = __float2half_rn(rm);
}

// ---------------------------------------------------------------------------
// helpers
// ---------------------------------------------------------------------------
__device__ __forceinline__ void mma_f16(float* d, const uint32_t* a,
                                        const uint32_t* b) {
    asm volatile(
        "mma.sync.aligned.m16n8k16.row.col.f32.f16.f16.f32 "
        "{%0,%1,%2,%3}, {%4,%5,%6,%7}, {%8,%9}, {%0,%1,%2,%3};"
        : "+f"(d[0]), "+f"(d[1]), "+f"(d[2]), "+f"(d[3])
        : "r"(a[0]), "r"(a[1]), "r"(a[2]), "r"(a[3]), "r"(b[0]), "r"(b[1]));
}
__device__ __forceinline__ void ldsm4(uint32_t* r, uint32_t addr) {
    asm volatile("ldmatrix.sync.aligned.m8n8.x4.shared.b16 {%0,%1,%2,%3}, [%4];"
                 : "=r"(r[0]), "=r"(r[1]), "=r"(r[2]), "=r"(r[3]) : "r"(addr));
}
__device__ __forceinline__ uint32_t smem_u32(const void* p) {
    uint32_t a;
    asm("{ .reg .u64 t; cvta.to.shared.u64 t, %1; cvt.u32.u64 %0, t; }"
        : "=r"(a) : "l"(p));
    return a;
}
__device__ __forceinline__ void cp16(uint32_t dst, const void* src) {
    asm volatile("cp.async.cg.shared.global [%0], [%1], 16;"
                 :: "r"(dst), "l"(src));
}
__device__ __forceinline__ int ld_acq(const int* p) {
    int v;
    asm volatile("ld.acquire.gpu.global.b32 %0, [%1];" : "=r"(v) : "l"(p) : "memory");
    return v;
}
__device__ __forceinline__ void red_release(int* p) {
    asm volatile("red.release.gpu.global.add.s32 [%0], 1;" :: "l"(p) : "memory");
}

// smem layout (union of both paths); rec needs the most: 207,872 B
#define TB_AH   0
#define TB_AM   16384
#define TB_BH   32768
#define TB_BM   49152
#define TB_SIZE 65536
#define GS_BIAS (2 * TB_SIZE)            // gemm path total: 131,584 B
// rec path (float offsets)
#define SM_W0   0
#define SM_W1   16384
#define SM_W2   32768
#define SM_W3   49152
#define SM_RCB1 51712
#define SM_B2C  51840
#define SM_FLOATS 51968
#define SMF_BYTES (SM_FLOATS * 4)        // 207,872 B

// ---------------------------------------------------------------------------
// Fused kernel: blocks 0..31 = recurrent LIF consumers (8 samples each);
// blocks 32..531 = gemm producer tiles in t-major order with flag release.
// ---------------------------------------------------------------------------
__global__ void __launch_bounds__(256, 1) fused_kernel(
    const float* __restrict__ x,    const float* __restrict__ b1,
    const float* __restrict__ rcW1, const float* __restrict__ rcb1,
    const float* __restrict__ W2,   const float* __restrict__ b2,
    const float* __restrict__ rcW2, const float* __restrict__ rcb2,
    const float* __restrict__ W3,   const float* __restrict__ b3,
    float* __restrict__ out)
{
    extern __shared__ char smg[];
    const int tid  = threadIdx.x;
    const int wid  = tid >> 5;
    const int lane = tid & 31;

    if (blockIdx.x >= REC_CTAS) {
        // =============== GEMM PRODUCER PATH ===============
        const uint32_t sbase = smem_u32(smg);
        const int g     = blockIdx.x - REC_CTAS;   // 0..499
        const int tcur  = g >> 1;                  // timestep this tile produces
        const int halfT = g & 1;                   // batch half
        const int mw    = wid & 1;
        const int nw    = wid >> 1;

        if (tid < 128) ((float*)(smg + GS_BIAS))[tid] = b1[tid];

        float acc[4][4][4];
        #pragma unroll
        for (int i = 0; i < 4; i++)
            #pragma unroll
            for (int j = 0; j < 4; j++)
                #pragma unroll
                for (int c = 0; c < 4; c++) acc[i][j][c] = 0.f;

        const int arow = tid >> 1;                 // local batch row 0..127
        const int akh  = tid & 1;
        const float* xrow = x + ((size_t)(halfT * 128 + arow) * Tsz + tcur) * DIN;
        const uint32_t aswz = (uint32_t)((arow & 7) << 4);
        const uint32_t abase = (uint32_t)(arow * 128);

        const int ra = (lane & 7) + ((lane >> 3) & 1) * 8;
        const int ka = (lane >> 4) * 8;
        const int rb = (lane & 7) + (lane >> 4) * 8;
        const int kbl = ((lane >> 3) & 1) * 8;
        const uint32_t lswz = (uint32_t)((lane & 7) << 4);

        int bn[4], bkc[4];
        uint32_t bdst[4];
        #pragma unroll
        for (int u = 0; u < 4; u++) {
            int c = tid + u * 256;
            bn[u]  = c >> 3;
            bkc[u] = c & 7;
            bdst[u] = (uint32_t)(bn[u] * 128)
                    + (((uint32_t)(bkc[u] * 16)) ^ ((uint32_t)((bn[u] & 7) << 4)));
        }

        float4 va[8];

        auto ldA = [&](int kt) {
            #pragma unroll
            for (int i = 0; i < 4; i++) {
                int kl = akh * 32 + i * 8;
                int gk = kt * KT + kl;
                va[i*2+0] = (gk <= DIN - 4) ? *(const float4*)(xrow + gk)
                                            : make_float4(0.f, 0.f, 0.f, 0.f);
                va[i*2+1] = (gk + 4 <= DIN - 4) ? *(const float4*)(xrow + gk + 4)
                                                : make_float4(0.f, 0.f, 0.f, 0.f);
            }
        };
        auto cpB = [&](int kt, uint32_t buf) {
            #pragma unroll
            for (int u = 0; u < 4; u++) {
                int src = kt * (128 * KT) + bn[u] * KT + bkc[u] * 8;
                cp16(buf + TB_BH + bdst[u], g_Bh + src);
                cp16(buf + TB_BM + bdst[u], g_Bm + src);
            }
            asm volatile("cp.async.commit_group;" ::: "memory");
        };
        auto stsA = [&](char* bufp) {
            #pragma unroll
            for (int i = 0; i < 4; i++) {
                int kl = akh * 32 + i * 8;
                float a[8];
                a[0]=va[i*2].x; a[1]=va[i*2].y; a[2]=va[i*2].z; a[3]=va[i*2].w;
                a[4]=va[i*2+1].x; a[5]=va[i*2+1].y; a[6]=va[i*2+1].z; a[7]=va[i*2+1].w;
                uint32_t hw[4], mw4[4];
                #pragma unroll
                for (int p = 0; p < 4; p++) {
                    __half2 h2 = __float22half2_rn(make_float2(a[2*p], a[2*p+1]));
                    float2 hf = __half22float2(h2);
                    __half2 m2 = __float22half2_rn(
                        make_float2(a[2*p] - hf.x, a[2*p+1] - hf.y));
                    hw[p]  = *reinterpret_cast<uint32_t*>(&h2);
                    mw4[p] = *reinterpret_cast<uint32_t*>(&m2);
                }
                uint32_t soff = abase + (((uint32_t)(kl * 2)) ^ aswz);
                *(uint4*)(bufp + TB_AH + soff) = make_uint4(hw[0],hw[1],hw[2],hw[3]);
                *(uint4*)(bufp + TB_AM + soff) = make_uint4(mw4[0],mw4[1],mw4[2],mw4[3]);
            }
        };

        ldA(0);
        cpB(0, sbase);
        stsA(smg);
        asm volatile("cp.async.wait_group 0;" ::: "memory");
        __syncthreads();

        for (int kt = 0; kt < NKT; kt++) {
            const uint32_t cbuf = (uint32_t)(kt & 1) * TB_SIZE;
            const uint32_t nbuf = (uint32_t)((kt + 1) & 1) * TB_SIZE;

            if (kt + 1 < NKT) {
                ldA(kt + 1);
                cpB(kt + 1, sbase + nbuf);
            }

            #pragma unroll
            for (int ks = 0; ks < 4; ks++) {
                const int kb = ks * 16;
                uint32_t ah[4][4], am[4][4], bh[4][2], bm[4][2];

                #pragma unroll
                for (int mt = 0; mt < 4; mt++) {
                    uint32_t row = (uint32_t)(mw * 64 + mt * 16 + ra);
                    uint32_t off = row * 128 + (((uint32_t)((kb + ka) * 2)) ^ lswz);
                    ldsm4(ah[mt], sbase + cbuf + TB_AH + off);
                    ldsm4(am[mt], sbase + cbuf + TB_AM + off);
                }
                #pragma unroll
                for (int g2 = 0; g2 < 2; g2++) {
                    uint32_t row = (uint32_t)(nw * 32 + g2 * 16 + rb);
                    uint32_t off = row * 128 + (((uint32_t)((kb + kbl) * 2)) ^ lswz);
                    uint32_t r4[4];
                    ldsm4(r4, sbase + cbuf + TB_BH + off);
                    bh[g2*2][0] = r4[0]; bh[g2*2][1] = r4[1];
                    bh[g2*2+1][0] = r4[2]; bh[g2*2+1][1] = r4[3];
                    ldsm4(r4, sbase + cbuf + TB_BM + off);
                    bm[g2*2][0] = r4[0]; bm[g2*2][1] = r4[1];
                    bm[g2*2+1][0] = r4[2]; bm[g2*2+1][1] = r4[3];
                }

                #pragma unroll
                for (int mt = 0; mt < 4; mt++)
                    #pragma unroll
                    for (int nt = 0; nt < 4; nt++) {
                        mma_f16(acc[mt][nt], am[mt], bh[nt]);   // mh
                        mma_f16(acc[mt][nt], ah[mt], bm[nt]);   // hm
                    }
                #pragma unroll
                for (int mt = 0; mt < 4; mt++)
                    #pragma unroll
                    for (int nt = 0; nt < 4; nt++)
                        mma_f16(acc[mt][nt], ah[mt], bh[nt]);   // hh
            }

            if (kt + 1 < NKT) {
                stsA(smg + nbuf);
                asm volatile("cp.async.wait_group 0;" ::: "memory");
                __syncthreads();
            }
        }

        // epilogue: h1[tcur][halfT*128 + r][c]
        const float* sb1 = (const float*)(smg + GS_BIAS);
        const int r_lo = lane >> 2;
        const int c_lo = (lane & 3) * 2;
        float* tbase = g_h1 + (size_t)tcur * (Bsz * Hd) + (size_t)(halfT * 128) * Hd;
        #pragma unroll
        for (int mt = 0; mt < 4; mt++) {
            #pragma unroll
            for (int hh8 = 0; hh8 < 2; hh8++) {
                int r = mw * 64 + mt * 16 + r_lo + hh8 * 8;
                float* orow = tbase + (size_t)r * Hd;
                #pragma unroll
                for (int nt = 0; nt < 4; nt++) {
                    int c = nw * 32 + nt * 8 + c_lo;
                    float2 v;
                    v.x = acc[mt][nt][hh8 * 2 + 0] + sb1[c];
                    v.y = acc[mt][nt][hh8 * 2 + 1] + sb1[c + 1];
                    *(float2*)(orow + c) = v;
                }
            }
        }

        // publish: this tile's half of timestep tcur is complete
        __threadfence();
        __syncthreads();
        if (tid == 0) red_release(&g_flag[tcur]);
        return;
    }

    // =============== RECURRENT CONSUMER PATH ===============
    float* sm    = (float*)smg;
    float* sW0   = sm + SM_W0;
    float* sW1   = sm + SM_W1;
    float* sW2   = sm + SM_W2;
    float* sW3   = sm + SM_W3;
    float* srcb1 = sm + SM_RCB1;
    float* sb2c  = sm + SM_B2C;

    {
        const float4* a = (const float4*)rcW1;
        const float4* c = (const float4*)W2;
        const float4* d = (const float4*)rcW2;
        float4* o0 = (float4*)sW0; float4* o1 = (float4*)sW1; float4* o2 = (float4*)sW2;
        for (int i = tid; i < (Hd * Hd) / 4; i += 256) {
            o0[i] = a[i]; o1[i] = c[i]; o2[i] = d[i];
        }
    }
    for (int i = tid; i < Hd * DOUT; i += 256) sW3[i] = W3[i];
    if (tid < Hd) {
        srcb1[tid] = rcb1[tid];
        sb2c[tid]  = b2[tid] + rcb2[tid];
    }
    __syncthreads();

    const int b  = blockIdx.x * 8 + wid;    // 8 samples per CTA, one per warp
    const int j0 = lane * 4;

    const float4 rcb1_r = *(const float4*)(srcb1 + j0);
    const float4 b2c_r  = *(const float4*)(sb2c + j0);

    float4 v1 = make_float4(0.f, 0.f, 0.f, 0.f);
    float4 v2 = make_float4(0.f, 0.f, 0.f, 0.f);
    float  acc = 0.f;
    unsigned m1[4] = {0u,0u,0u,0u};
    unsigned m2[4] = {0u,0u,0u,0u};

    const float* h1p = g_h1 + b * Hd + j0;

    const float* sW0j = sW0 + j0;
    const float* sW1j = sW1 + j0;
    const float* sW2j = sW2 + j0;

    // flag prefetch ring: fr[k&3] holds g_flag[k] for k = t+1 at step t
    int fr[4];
    #pragma unroll
    for (int k = 1; k <= 4; k++) fr[k & 3] = ld_acq(&g_flag[k]);

    // gate t = 0
    while (ld_acq(&g_flag[0]) < 2) __nanosleep(64);
    float4 h1v = *(const float4*)h1p;

    for (int t = 0; t < Tsz; t++) {
        // ---- phase 1: u = h1 + rcb1 + y1_old @ rcW1 ----
        float4 u;
        u.x = h1v.x + rcb1_r.x; u.y = h1v.y + rcb1_r.y;
        u.z = h1v.z + rcb1_r.z; u.w = h1v.w + rcb1_r.w;
        #pragma unroll
        for (int c = 0; c < 4; c++) {
            unsigned mm = m1[c];
            while (mm) {
                int bit = __ffs(mm) - 1; mm &= mm - 1u;
                float4 w = *(const float4*)(sW0j + ((bit << 2) | c) * Hd);
                u.x += w.x; u.y += w.y; u.z += w.z; u.w += w.w;
            }
        }
        v1.x += (u.x - v1.x) * 0.5f;  v1.y += (u.y - v1.y) * 0.5f;
        v1.z += (u.z - v1.z) * 0.5f;  v1.w += (u.w - v1.w) * 0.5f;
        bool s0 = v1.x >= 1.f, s1b = v1.y >= 1.f, s2b = v1.z >= 1.f, s3 = v1.w >= 1.f;
        if (s0) v1.x = 0.f;  if (s1b) v1.y = 0.f;
        if (s2b) v1.z = 0.f; if (s3) v1.w = 0.f;
        m1[0] = __ballot_sync(0xffffffffu, s0);
        m1[1] = __ballot_sync(0xffffffffu, s1b);
        m1[2] = __ballot_sync(0xffffffffu, s2b);
        m1[3] = __ballot_sync(0xffffffffu, s3);

        // ---- gate + prefetch h1 for t+1 (overlaps phase 2) ----
        float4 h1n = make_float4(0.f, 0.f, 0.f, 0.f);
        if (t + 1 < Tsz) {
            int f = fr[(t + 1) & 3];
            if (f < 2) {
                while ((f = ld_acq(&g_flag[t + 1])) < 2) __nanosleep(64);
            }
            h1n = *(const float4*)(h1p + (size_t)(t + 1) * (Bsz * Hd));
            if (t + 5 < Tsz) fr[(t + 1) & 3] = ld_acq(&g_flag[t + 5]);
        }

        // ---- phase 2: u2 = b2 + rcb2 + y1_new @ W2 + y2_old @ rcW2 ----
        float4 u2 = make_float4(b2c_r.x, b2c_r.y, b2c_r.z, b2c_r.w);
        #pragma unroll
        for (int c = 0; c < 4; c++) {
            unsigned mm = m1[c];
            while (mm) {
                int bit = __ffs(mm) - 1; mm &= mm - 1u;
                float4 w = *(const float4*)(sW1j + ((bit << 2) | c) * Hd);
                u2.x += w.x; u2.y += w.y; u2.z += w.z; u2.w += w.w;
            }
        }
        #pragma unroll
        for (int c = 0; c < 4; c++) {
            unsigned mm = m2[c];
            while (mm) {
                int bit = __ffs(mm) - 1; mm &= mm - 1u;
                float4 w = *(const float4*)(sW2j + ((bit << 2) | c) * Hd);
                u2.x += w.x; u2.y += w.y; u2.z += w.z; u2.w += w.w;
            }
        }
        v2.x += (u2.x - v2.x) * 0.5f;  v2.y += (u2.y - v2.y) * 0.5f;
        v2.z += (u2.z - v2.z) * 0.5f;  v2.w += (u2.w - v2.w) * 0.5f;
        s0 = v2.x >= 1.f; s1b = v2.y >= 1.f; s2b = v2.z >= 1.f; s3 = v2.w >= 1.f;
        if (s0) v2.x = 0.f;  if (s1b) v2.y = 0.f;
        if (s2b) v2.z = 0.f; if (s3) v2.w = 0.f;
        m2[0] = __ballot_sync(0xffffffffu, s0);
        m2[1] = __ballot_sync(0xffffffffu, s1b);
        m2[2] = __ballot_sync(0xffffffffu, s2b);
        m2[3] = __ballot_sync(0xffffffffu, s3);

        // ---- readout: acc += y2_new @ W3 ----
        if (lane < DOUT) {
            float a = 0.f;
            #pragma unroll
            for (int c = 0; c < 4; c++) {
                unsigned mm = m2[c];
                while (mm) {
                    int bit = __ffs(mm) - 1; mm &= mm - 1u;
                    a += sW3[((bit << 2) | c) * DOUT + lane];
                }
            }
            acc += a;
        }
        h1v = h1n;
    }

    if (lane < DOUT)
        out[b * DOUT + lane] = acc + (float)Tsz * b3[lane];
}

// ---------------------------------------------------------------------------
// Launch
// ---------------------------------------------------------------------------
extern "C" void kernel_launch(void* const* d_in, const int* in_sizes, int n_in,
                              void* d_out, int out_size)
{
    const float* x    = (const float*)d_in[0];
    const float* W1   = (const float*)d_in[1];
    const float* b1   = (const float*)d_in[2];
    const float* rcW1 = (const float*)d_in[3];
    const float* rcb1 = (const float*)d_in[4];
    const float* W2   = (const float*)d_in[5];
    const float* b2   = (const float*)d_in[6];
    const float* rcW2 = (const float*)d_in[7];
    const float* rcb2 = (const float*)d_in[8];
    const float* W3   = (const float*)d_in[9];
    const float* b3   = (const float*)d_in[10];
    float* out = (float*)d_out;

    cudaFuncSetAttribute(fused_kernel,
                         cudaFuncAttributeMaxDynamicSharedMemorySize, SMF_BYTES);

    // 0) fp16 split of W1 + zero the timestep flags (every replay)
    prep_kernel<<<(NKT * 128 * KT + 255) / 256, 256>>>(W1);

    // 1) fused producer/consumer: 32 rec CTAs + 500 t-major gemm tiles
    fused_kernel<<<REC_CTAS + GEMM_TILES, 256, SMF_BYTES>>>(
        x, b1, rcW1, rcb1, W2, b2, rcW2, rcb2, W3, b3, out);
}